// round 4
// baseline (speedup 1.0000x reference)
#include <cuda_runtime.h>
#include <cuda_bf16.h>
#include <cstdint>

// Problem constants (shape fixed by dataset: img [64, 3, 512, 512])
constexpr int NCH = 64 * 3;        // 192 channels
constexpr int P   = 512 * 512;     // 262144 pixels / channel
constexpr int NB  = 256;           // bins

// Scratch (no cudaMalloc allowed) — __device__ globals
__device__ int           g_hist[NCH * NB];     // zero-initialized at load; lut_kernel re-zeroes
__device__ float         g_lut [NCH * NB];
__device__ unsigned char g_u8  [(size_t)NCH * P];  // 50.3 MB packed bin scratch

// ---------------------------------------------------------------------------
// Kernel 1: histogram + quantize-to-uint8. grid = (HB, NCH), 256 threads.
// Reads float4 input with streaming hint (protect L2 for the uint8 scratch),
// accumulates 8-way privatized shared histograms, writes packed uchar4 bins.
// ---------------------------------------------------------------------------
constexpr int HB = 32;  // blocks per channel

__global__ void hist_quant_kernel(const float* __restrict__ in) {
    __shared__ int sh[NB * 8];
    const int c = blockIdx.y;

    for (int i = threadIdx.x; i < NB * 8; i += blockDim.x) sh[i] = 0;
    __syncthreads();

    const float4* bi = reinterpret_cast<const float4*>(in + (size_t)c * P);
    unsigned int* bo = reinterpret_cast<unsigned int*>(g_u8 + (size_t)c * P);
    const int n = (P / 4) / HB;             // 2048 float4 per block
    const int start = blockIdx.x * n;
    const int sub = threadIdx.x & 7;

    for (int i = threadIdx.x; i < n; i += blockDim.x) {
        float4 v = __ldcs(&bi[start + i]);   // evict-first: don't pollute L2
        int b0 = (int)v.x, b1 = (int)v.y, b2 = (int)v.z, b3 = (int)v.w;
        atomicAdd(&sh[b0 * 8 + sub], 1);
        atomicAdd(&sh[b1 * 8 + sub], 1);
        atomicAdd(&sh[b2 * 8 + sub], 1);
        atomicAdd(&sh[b3 * 8 + sub], 1);
        bo[start + i] = (unsigned)b0 | ((unsigned)b1 << 8) |
                        ((unsigned)b2 << 16) | ((unsigned)b3 << 24);
    }
    __syncthreads();

    for (int b = threadIdx.x; b < NB; b += blockDim.x) {
        int s = 0;
#pragma unroll
        for (int k = 0; k < 8; k++) s += sh[b * 8 + k];
        atomicAdd(&g_hist[c * NB + b], s);
    }
}

// ---------------------------------------------------------------------------
// Kernel 2: build per-channel LUT (exact PIL integer math), then re-zero the
// histogram so the next graph replay starts clean (replaces zero kernel).
//   step = (P - last_nonzero_val) / 255
//   lut[i] = step==0 ? i : clamp((cs[i-1] + step/2) / max(step,1), 0, 255)
// (step==0 passthrough folded into identity LUT — inputs are exact integers)
// ---------------------------------------------------------------------------
__global__ void lut_kernel() {
    const int c = blockIdx.x;
    const int i = threadIdx.x;

    __shared__ int h[NB];
    __shared__ int cs[NB];
    __shared__ int red[NB];

    const int hv = g_hist[c * NB + i];
    h[i]  = hv;
    cs[i] = hv;
    __syncthreads();

    // Inclusive Hillis-Steele scan over 256 elements
#pragma unroll
    for (int off = 1; off < NB; off <<= 1) {
        int v = (i >= off) ? cs[i - off] : 0;
        __syncthreads();
        cs[i] += v;
        __syncthreads();
    }

    // Last nonzero bin index
    red[i] = (hv != 0) ? i : -1;
    __syncthreads();
#pragma unroll
    for (int s = 128; s > 0; s >>= 1) {
        if (i < s) red[i] = max(red[i], red[i + s]);
        __syncthreads();
    }
    const int last_idx = red[0];
    const int last_val = h[last_idx];

    const int step = (P - last_val) / 255;
    const int safe = step > 0 ? step : 1;

    const int prev = (i == 0) ? 0 : cs[i - 1];
    int lv = (prev + step / 2) / safe;
    lv = min(max(lv, 0), 255);
    if (step == 0) lv = i;                   // passthrough as identity LUT
    g_lut[c * NB + i] = (float)lv;

    g_hist[c * NB + i] = 0;                  // clean for next replay
}

// ---------------------------------------------------------------------------
// Kernel 3: apply LUT from uint8 scratch. grid = (AB, NCH), 256 threads.
// Each thread: one uint4 (16 packed pixels) -> 4 float4 streaming stores.
// ---------------------------------------------------------------------------
constexpr int AB = 64;  // blocks per channel

__global__ void apply_kernel(float* __restrict__ out) {
    __shared__ float slut[NB];
    const int c = blockIdx.y;
    if (threadIdx.x < NB) slut[threadIdx.x] = g_lut[c * NB + threadIdx.x];
    __syncthreads();

    const uint4* bi = reinterpret_cast<const uint4*>(g_u8 + (size_t)c * P);
    float4*      bo = reinterpret_cast<float4*>(out + (size_t)c * P);
    const int n = (P / 16) / AB;             // 256 uint4 per block
    const int start = blockIdx.x * n;

    for (int i = threadIdx.x; i < n; i += blockDim.x) {
        uint4 w = bi[start + i];
        float4 o0, o1, o2, o3;
        o0.x = slut[ w.x        & 255]; o0.y = slut[(w.x >>  8) & 255];
        o0.z = slut[(w.x >> 16) & 255]; o0.w = slut[(w.x >> 24)      ];
        o1.x = slut[ w.y        & 255]; o1.y = slut[(w.y >>  8) & 255];
        o1.z = slut[(w.y >> 16) & 255]; o1.w = slut[(w.y >> 24)      ];
        o2.x = slut[ w.z        & 255]; o2.y = slut[(w.z >>  8) & 255];
        o2.z = slut[(w.z >> 16) & 255]; o2.w = slut[(w.z >> 24)      ];
        o3.x = slut[ w.w        & 255]; o3.y = slut[(w.w >>  8) & 255];
        o3.z = slut[(w.w >> 16) & 255]; o3.w = slut[(w.w >> 24)      ];
        const int ob = (start + i) * 4;
        __stcs(&bo[ob + 0], o0);             // evict-first: keep scratch in L2
        __stcs(&bo[ob + 1], o1);
        __stcs(&bo[ob + 2], o2);
        __stcs(&bo[ob + 3], o3);
    }
}

// ---------------------------------------------------------------------------
extern "C" void kernel_launch(void* const* d_in, const int* in_sizes, int n_in,
                              void* d_out, int out_size) {
    const float* img = (const float*)d_in[0];
    float* out = (float*)d_out;

    hist_quant_kernel<<<dim3(HB, NCH), 256>>>(img);
    lut_kernel<<<NCH, 256>>>();
    apply_kernel<<<dim3(AB, NCH), 256>>>(out);
}

// round 5
// speedup vs baseline: 1.1235x; 1.1235x over previous
#include <cuda_runtime.h>
#include <cuda_bf16.h>
#include <cstdint>

// Problem constants (shape fixed by dataset: img [64, 3, 512, 512])
constexpr int NCH = 64 * 3;        // 192 channels
constexpr int P   = 512 * 512;     // 262144 pixels / channel
constexpr int NB  = 256;           // bins

// Scratch (no cudaMalloc allowed) — __device__ globals
// g_hist starts zero (static init) and lut_kernel re-zeroes it each replay.
__device__ int   g_hist[NCH * NB];
__device__ float g_lut [NCH * NB];

// ---------------------------------------------------------------------------
// Kernel 1: per-channel histogram. grid = (HB, NCH), 256 threads (8 warps).
// Per-warp private shared histograms -> zero cross-warp atomic interference.
// 2x float4 per thread per iteration for MLP.
// ---------------------------------------------------------------------------
constexpr int HB = 32;  // blocks per channel

__global__ void hist_kernel(const float* __restrict__ in) {
    __shared__ int sh[8 * NB];             // 8 KB: one 256-bin hist per warp
    const int c    = blockIdx.y;
    const int warp = threadIdx.x >> 5;
    int* const myh = &sh[warp * NB];

    for (int i = threadIdx.x; i < 8 * NB; i += blockDim.x) sh[i] = 0;
    __syncthreads();

    const float4* base = reinterpret_cast<const float4*>(in + (size_t)c * P);
    const int n = (P / 4) / HB;            // 2048 float4 per block
    const int start = blockIdx.x * n;

    // 2048 / 256 = 8 iterations -> 4 double-iterations, 2 loads in flight
    for (int i = threadIdx.x; i < n; i += 2 * blockDim.x) {
        float4 a = base[start + i];
        float4 b = base[start + i + blockDim.x];
        atomicAdd(&myh[(int)a.x], 1);
        atomicAdd(&myh[(int)a.y], 1);
        atomicAdd(&myh[(int)a.z], 1);
        atomicAdd(&myh[(int)a.w], 1);
        atomicAdd(&myh[(int)b.x], 1);
        atomicAdd(&myh[(int)b.y], 1);
        atomicAdd(&myh[(int)b.z], 1);
        atomicAdd(&myh[(int)b.w], 1);
    }
    __syncthreads();

    // Reduce 8 warp-hists -> global
    {
        const int b = threadIdx.x;         // 256 threads == 256 bins
        int s = 0;
#pragma unroll
        for (int k = 0; k < 8; k++) s += sh[k * NB + b];
        if (s) atomicAdd(&g_hist[c * NB + b], s);
    }
}

// ---------------------------------------------------------------------------
// Kernel 2: build per-channel LUT (exact PIL integer math), then re-zero the
// histogram so the next graph replay starts clean.
//   step = (P - last_nonzero_val) / 255
//   lut[i] = step==0 ? i : clamp((cs[i-1] + step/2) / max(step,1), 0, 255)
// (step==0 passthrough folded into identity LUT — inputs are exact integers)
// ---------------------------------------------------------------------------
__global__ void lut_kernel() {
    const int c = blockIdx.x;
    const int i = threadIdx.x;

    __shared__ int h[NB];
    __shared__ int cs[NB];
    __shared__ int red[NB];

    const int hv = g_hist[c * NB + i];
    h[i]  = hv;
    cs[i] = hv;
    __syncthreads();

    // Inclusive Hillis-Steele scan over 256 elements
#pragma unroll
    for (int off = 1; off < NB; off <<= 1) {
        int v = (i >= off) ? cs[i - off] : 0;
        __syncthreads();
        cs[i] += v;
        __syncthreads();
    }

    // Last nonzero bin index
    red[i] = (hv != 0) ? i : -1;
    __syncthreads();
#pragma unroll
    for (int s = 128; s > 0; s >>= 1) {
        if (i < s) red[i] = max(red[i], red[i + s]);
        __syncthreads();
    }
    const int last_idx = red[0];
    const int last_val = h[last_idx];

    const int step = (P - last_val) / 255;
    const int safe = step > 0 ? step : 1;

    const int prev = (i == 0) ? 0 : cs[i - 1];
    int lv = (prev + step / 2) / safe;
    lv = min(max(lv, 0), 255);
    if (step == 0) lv = i;                 // passthrough as identity LUT
    g_lut[c * NB + i] = (float)lv;

    g_hist[c * NB + i] = 0;                // clean for next replay
}

// ---------------------------------------------------------------------------
// Kernel 3: apply LUT. grid = (AB, NCH), 256 threads, float4 I/O.
// REVERSED traversal: hist_kernel just streamed the input through L2 in
// ascending order, so the tail (~120MB) is resident. Reading newest-first
// converts those re-reads into L2 hits. __stcs on the 201MB output stream
// keeps the write data from evicting the resident input.
// ---------------------------------------------------------------------------
constexpr int AB = 64;  // blocks per channel

__global__ void apply_kernel(const float* __restrict__ in, float* __restrict__ out) {
    __shared__ float slut[NB];

    const int c  = (NCH - 1) - blockIdx.y;             // reversed channel order
    const int bx = (AB  - 1) - blockIdx.x;             // reversed within channel

    slut[threadIdx.x] = g_lut[c * NB + threadIdx.x];
    __syncthreads();

    const float4* bi = reinterpret_cast<const float4*>(in  + (size_t)c * P);
    float4*       bo = reinterpret_cast<float4*>      (out + (size_t)c * P);
    const int n = (P / 4) / AB;            // 1024 float4 per block
    const int start = bx * n;

    for (int i = threadIdx.x; i < n; i += 2 * blockDim.x) {
        float4 a = bi[start + i];
        float4 b = bi[start + i + blockDim.x];
        float4 oa, ob;
        oa.x = slut[(int)a.x]; oa.y = slut[(int)a.y];
        oa.z = slut[(int)a.z]; oa.w = slut[(int)a.w];
        ob.x = slut[(int)b.x]; ob.y = slut[(int)b.y];
        ob.z = slut[(int)b.z]; ob.w = slut[(int)b.w];
        __stcs(&bo[start + i], oa);
        __stcs(&bo[start + i + blockDim.x], ob);
    }
}

// ---------------------------------------------------------------------------
extern "C" void kernel_launch(void* const* d_in, const int* in_sizes, int n_in,
                              void* d_out, int out_size) {
    const float* img = (const float*)d_in[0];
    float* out = (float*)d_out;

    hist_kernel<<<dim3(HB, NCH), 256>>>(img);
    lut_kernel<<<NCH, 256>>>();
    apply_kernel<<<dim3(AB, NCH), 256>>>(img, out);
}